// round 4
// baseline (speedup 1.0000x reference)
#include <cuda_runtime.h>
#include <cuda_bf16.h>
#include <cstdint>

#define N_NODES 100000
#define N_EDGES 1600000
#define DIM 128

#define NODES_PER_SCAN_BLOCK 1024
#define N_SCAN_BLOCKS ((N_NODES + NODES_PER_SCAN_BLOCK - 1) / NODES_PER_SCAN_BLOCK)  // 98

// ---------------- static device scratch (no runtime allocation) ----------------
__device__ int   g_cnt[N_NODES];     // in-degree
__device__ int   g_cur[N_NODES];     // fill cursors
__device__ int   g_off[N_NODES];     // CSR row offsets (exclusive prefix of cnt)
__device__ int   g_csr[N_EDGES];     // CSR column (src) indices
__device__ float g_norm[N_NODES];
__device__ int   g_bsum[128];
__device__ int   g_boff[128];

// ---------------- kernel 1: zero counters ----------------
__global__ void zero_kernel() {
    int i = blockIdx.x * blockDim.x + threadIdx.x;
    int stride = gridDim.x * blockDim.x;
    for (int j = i; j < N_NODES; j += stride) { g_cnt[j] = 0; g_cur[j] = 0; }
}

// ---------------- kernel 2: in-degree histogram (int atomics) ----------------
__global__ void deg_kernel(const int* __restrict__ edst) {
    int e = blockIdx.x * blockDim.x + threadIdx.x;
    if (e < N_EDGES) atomicAdd(&g_cnt[edst[e]], 1);
}

// ---------------- scan pass 1: per-block sums of 1024 counts ----------------
__global__ __launch_bounds__(256) void scan1_kernel() {
    int b = blockIdx.x, t = threadIdx.x;
    int base = b * NODES_PER_SCAN_BLOCK + t * 4;
    int s = 0;
#pragma unroll
    for (int q = 0; q < 4; q++) {
        int n = base + q;
        if (n < N_NODES) s += g_cnt[n];
    }
#pragma unroll
    for (int o = 16; o > 0; o >>= 1) s += __shfl_down_sync(0xffffffffu, s, o);
    __shared__ int ws[8];
    if ((t & 31) == 0) ws[t >> 5] = s;
    __syncthreads();
    if (t == 0) {
        int tot = 0;
#pragma unroll
        for (int i = 0; i < 8; i++) tot += ws[i];
        g_bsum[b] = tot;
    }
}

// ---------------- scan pass 2: exclusive scan of block sums (1 block) ----------------
__global__ __launch_bounds__(128) void scan2_kernel() {
    int t = threadIdx.x;
    int lane = t & 31, wid = t >> 5;
    int v = (t < N_SCAN_BLOCKS) ? g_bsum[t] : 0;
    int x = v;
#pragma unroll
    for (int o = 1; o < 32; o <<= 1) {
        int y = __shfl_up_sync(0xffffffffu, x, o);
        if (lane >= o) x += y;
    }
    __shared__ int wsum[4];
    if (lane == 31) wsum[wid] = x;
    __syncthreads();
    if (t == 0) {
        int r = 0;
#pragma unroll
        for (int i = 0; i < 4; i++) { int tmp = wsum[i]; wsum[i] = r; r += tmp; }
    }
    __syncthreads();
    int incl = x + wsum[wid];
    if (t < N_SCAN_BLOCKS) g_boff[t] = incl - v;   // exclusive
}

// ---------------- scan pass 3: per-node exclusive offsets + norm ----------------
__global__ __launch_bounds__(256) void scan3_kernel() {
    int b = blockIdx.x, t = threadIdx.x;
    int lane = t & 31, wid = t >> 5;
    int base = b * NODES_PER_SCAN_BLOCK + t * 4;
    int c[4];
    int tsum = 0;
#pragma unroll
    for (int q = 0; q < 4; q++) {
        c[q] = (base + q < N_NODES) ? g_cnt[base + q] : 0;
        tsum += c[q];
    }
    int x = tsum;
#pragma unroll
    for (int o = 1; o < 32; o <<= 1) {
        int y = __shfl_up_sync(0xffffffffu, x, o);
        if (lane >= o) x += y;
    }
    __shared__ int wsum[8], woff[8];
    if (lane == 31) wsum[wid] = x;
    __syncthreads();
    if (t == 0) {
        int r = 0;
#pragma unroll
        for (int i = 0; i < 8; i++) { woff[i] = r; r += wsum[i]; }
    }
    __syncthreads();
    int run = (x - tsum) + woff[wid] + g_boff[b];
#pragma unroll
    for (int q = 0; q < 4; q++) {
        int n = base + q;
        if (n < N_NODES) {
            g_off[n] = run;
            g_norm[n] = rsqrtf(fmaxf((float)c[q], 1.0f));
        }
        run += c[q];
    }
}

// ---------------- CSR fill ----------------
__global__ void fill_kernel(const int* __restrict__ esrc, const int* __restrict__ edst) {
    int e = blockIdx.x * blockDim.x + threadIdx.x;
    if (e < N_EDGES) {
        int d = edst[e];
        int pos = atomicAdd(&g_cur[d], 1);
        g_csr[g_off[d] + pos] = esrc[e];
    }
}

// ---------------- fused aggregate + GEMM ----------------
// Block = 64 dst rows. Phase 1: warps pull-aggregate rows into smem (no atomics),
// edge loop unrolled x4 for 4 outstanding 512B gathers per warp.
// Phase 2: register-tiled GEMM (TM=8, TN=4) against W, bias epilogue.
#define BM 64
#define A_PAD 132

__global__ __launch_bounds__(256) void fused_kernel(const float* __restrict__ h,
                                                    const float* __restrict__ W,
                                                    const float* __restrict__ bias,
                                                    float* __restrict__ out) {
    __shared__ float As[BM][A_PAD];
    __shared__ float Bs[8][128];

    int tid = threadIdx.x;
    int wid = tid >> 5;
    int lane = tid & 31;
    int block_m = blockIdx.x * BM;

    // ---- phase 1: aggregation. Warp w handles rows w, w+8, ..., w+56.
    for (int r = wid; r < BM; r += 8) {
        int gm = block_m + r;
        float4 acc = make_float4(0.f, 0.f, 0.f, 0.f);
        if (gm < N_NODES) {
            int beg = __ldg(&g_off[gm]);
            int deg = __ldg(&g_cnt[gm]);
            int end = beg + deg;
            int j = beg;
            // unrolled x4: batch 4 independent row gathers per iteration
            for (; j + 4 <= end; j += 4) {
                int s0 = __ldg(&g_csr[j + 0]);
                int s1 = __ldg(&g_csr[j + 1]);
                int s2 = __ldg(&g_csr[j + 2]);
                int s3 = __ldg(&g_csr[j + 3]);
                float n0 = __ldg(&g_norm[s0]);
                float n1 = __ldg(&g_norm[s1]);
                float n2 = __ldg(&g_norm[s2]);
                float n3 = __ldg(&g_norm[s3]);
                float4 v0 = __ldg(&((const float4*)(h + (size_t)s0 * DIM))[lane]);
                float4 v1 = __ldg(&((const float4*)(h + (size_t)s1 * DIM))[lane]);
                float4 v2 = __ldg(&((const float4*)(h + (size_t)s2 * DIM))[lane]);
                float4 v3 = __ldg(&((const float4*)(h + (size_t)s3 * DIM))[lane]);
                acc.x = fmaf(v0.x, n0, acc.x); acc.y = fmaf(v0.y, n0, acc.y);
                acc.z = fmaf(v0.z, n0, acc.z); acc.w = fmaf(v0.w, n0, acc.w);
                acc.x = fmaf(v1.x, n1, acc.x); acc.y = fmaf(v1.y, n1, acc.y);
                acc.z = fmaf(v1.z, n1, acc.z); acc.w = fmaf(v1.w, n1, acc.w);
                acc.x = fmaf(v2.x, n2, acc.x); acc.y = fmaf(v2.y, n2, acc.y);
                acc.z = fmaf(v2.z, n2, acc.z); acc.w = fmaf(v2.w, n2, acc.w);
                acc.x = fmaf(v3.x, n3, acc.x); acc.y = fmaf(v3.y, n3, acc.y);
                acc.z = fmaf(v3.z, n3, acc.z); acc.w = fmaf(v3.w, n3, acc.w);
            }
            for (; j < end; j++) {
                int s = __ldg(&g_csr[j]);
                float ns = __ldg(&g_norm[s]);
                float4 v = __ldg(&((const float4*)(h + (size_t)s * DIM))[lane]);
                acc.x = fmaf(v.x, ns, acc.x); acc.y = fmaf(v.y, ns, acc.y);
                acc.z = fmaf(v.z, ns, acc.z); acc.w = fmaf(v.w, ns, acc.w);
            }
            float nd = __ldg(&g_norm[gm]);
            acc.x *= nd; acc.y *= nd; acc.z *= nd; acc.w *= nd;
        }
        *(float4*)&As[r][lane * 4] = acc;
    }
    __syncthreads();

    // ---- phase 2: GEMM out[64x128] = As @ W^T + b
    int tm = tid >> 5;   // 0..7 (uniform within warp -> As reads broadcast)
    int tn = tid & 31;   // 0..31 (float4 Bs reads conflict-free)

    float facc[8][4];
#pragma unroll
    for (int i = 0; i < 8; i++)
#pragma unroll
        for (int j = 0; j < 4; j++) facc[i][j] = 0.f;

    for (int k0 = 0; k0 < DIM; k0 += 8) {
        // load W tile: Bs[k][j] = W[j][k0+k]
        {
            int j = tid >> 1;
            int koff = (tid & 1) * 4;
            float4 w = *(const float4*)(W + (size_t)j * DIM + k0 + koff);
            Bs[koff + 0][j] = w.x;
            Bs[koff + 1][j] = w.y;
            Bs[koff + 2][j] = w.z;
            Bs[koff + 3][j] = w.w;
        }
        __syncthreads();

#pragma unroll
        for (int k = 0; k < 8; k++) {
            float4 b4 = *(const float4*)&Bs[k][tn * 4];
            float bb[4] = { b4.x, b4.y, b4.z, b4.w };
#pragma unroll
            for (int i = 0; i < 8; i++) {
                float a = As[tm * 8 + i][k0 + k];   // warp-uniform broadcast
#pragma unroll
                for (int j = 0; j < 4; j++) facc[i][j] += a * bb[j];
            }
        }
        __syncthreads();
    }

    // ---- epilogue
    float4 bv = *(const float4*)(bias + tn * 4);
#pragma unroll
    for (int i = 0; i < 8; i++) {
        int gm = block_m + tm * 8 + i;
        if (gm < N_NODES) {
            float4 r;
            r.x = facc[i][0] + bv.x;
            r.y = facc[i][1] + bv.y;
            r.z = facc[i][2] + bv.z;
            r.w = facc[i][3] + bv.w;
            *(float4*)(out + (size_t)gm * DIM + tn * 4) = r;
        }
    }
}

// ---------------- launch ----------------
extern "C" void kernel_launch(void* const* d_in, const int* in_sizes, int n_in,
                              void* d_out, int out_size) {
    const float* h    = (const float*)d_in[0];
    const float* W    = (const float*)d_in[1];
    const float* bias = (const float*)d_in[2];
    const int* esrc   = (const int*)d_in[3];
    const int* edst   = (const int*)d_in[4];
    float* out = (float*)d_out;

    zero_kernel<<<256, 256>>>();
    deg_kernel<<<(N_EDGES + 255) / 256, 256>>>(edst);
    scan1_kernel<<<N_SCAN_BLOCKS, 256>>>();
    scan2_kernel<<<1, 128>>>();
    scan3_kernel<<<N_SCAN_BLOCKS, 256>>>();
    fill_kernel<<<(N_EDGES + 255) / 256, 256>>>(esrc, edst);
    fused_kernel<<<(N_NODES + BM - 1) / BM, 256>>>(h, W, bias, out);
}

// round 6
// speedup vs baseline: 1.0962x; 1.0962x over previous
#include <cuda_runtime.h>
#include <cuda_bf16.h>
#include <cstdint>

#define N_NODES 100000
#define N_EDGES 1600000
#define DIM 128

#define NODES_PER_SCAN_BLOCK 1024
#define N_SCAN_BLOCKS ((N_NODES + NODES_PER_SCAN_BLOCK - 1) / NODES_PER_SCAN_BLOCK)  // 98

// ---------------- static device scratch (no runtime allocation) ----------------
__device__ int    g_cnt[N_NODES];
__device__ int    g_cur[N_NODES];
__device__ int    g_off[N_NODES];
__device__ int    g_csr[N_EDGES];
__device__ float  g_norm[N_NODES];
__device__ int    g_bsum[128];
__device__ int    g_boff[128];
// W packed in mma B-fragment order: [ks=16][nfrag=16][lane=32] x {b0hi,b1hi,b0lo,b1lo}
__device__ float4 g_wpack[16 * 16 * 32];

// ---------------- helpers ----------------
__device__ __forceinline__ uint32_t f2tf32(float x) {
    uint32_t r;
    asm("cvt.rna.tf32.f32 %0, %1;" : "=r"(r) : "f"(x));
    return r;
}
__device__ __forceinline__ void cpasync16(void* dst_smem, const void* src) {
    uint32_t d = (uint32_t)__cvta_generic_to_shared(dst_smem);
    asm volatile("cp.async.cg.shared.global [%0], [%1], 16;" :: "r"(d), "l"(src));
}
#define CP_COMMIT() asm volatile("cp.async.commit_group;")
#define CP_WAIT1()  asm volatile("cp.async.wait_group 1;")

__device__ __forceinline__ void mma_tf32(float* d, const uint32_t* a, uint32_t b0, uint32_t b1) {
    asm volatile(
        "mma.sync.aligned.m16n8k8.row.col.f32.tf32.tf32.f32 "
        "{%0,%1,%2,%3}, {%4,%5,%6,%7}, {%8,%9}, {%0,%1,%2,%3};"
        : "+f"(d[0]), "+f"(d[1]), "+f"(d[2]), "+f"(d[3])
        : "r"(a[0]), "r"(a[1]), "r"(a[2]), "r"(a[3]), "r"(b0), "r"(b1));
}

// ---------------- kernel 1: zero counters ----------------
__global__ void zero_kernel() {
    int i = blockIdx.x * blockDim.x + threadIdx.x;
    int stride = gridDim.x * blockDim.x;
    for (int j = i; j < N_NODES; j += stride) { g_cnt[j] = 0; g_cur[j] = 0; }
}

// ---------------- kernel 2: in-degree histogram ----------------
__global__ void deg_kernel(const int* __restrict__ edst) {
    int e = blockIdx.x * blockDim.x + threadIdx.x;
    if (e < N_EDGES) atomicAdd(&g_cnt[edst[e]], 1);
}

// ---------------- W pack: split into tf32 hi/lo, fragment order ----------------
__global__ void wpack_kernel(const float* __restrict__ W) {
    int t = blockIdx.x * blockDim.x + threadIdx.x;   // 0..8191
    if (t >= 16 * 16 * 32) return;
    int lane = t & 31;
    int f    = (t >> 5) & 15;
    int ks   = t >> 9;
    int g  = lane >> 2;
    int tg = lane & 3;
    int n = f * 8 + g;
    int k = ks * 8 + tg;
    float w0 = W[n * DIM + k];
    float w1 = W[n * DIM + k + 4];
    uint32_t h0 = f2tf32(w0);
    uint32_t h1 = f2tf32(w1);
    float l0 = w0 - __uint_as_float(h0);
    float l1 = w1 - __uint_as_float(h1);
    float4 v;
    v.x = __uint_as_float(h0);
    v.y = __uint_as_float(h1);
    v.z = __uint_as_float(f2tf32(l0));
    v.w = __uint_as_float(f2tf32(l1));
    g_wpack[t] = v;
}

// ---------------- scan pass 1 ----------------
__global__ __launch_bounds__(256) void scan1_kernel() {
    int b = blockIdx.x, t = threadIdx.x;
    int base = b * NODES_PER_SCAN_BLOCK + t * 4;
    int s = 0;
#pragma unroll
    for (int q = 0; q < 4; q++) {
        int n = base + q;
        if (n < N_NODES) s += g_cnt[n];
    }
#pragma unroll
    for (int o = 16; o > 0; o >>= 1) s += __shfl_down_sync(0xffffffffu, s, o);
    __shared__ int ws[8];
    if ((t & 31) == 0) ws[t >> 5] = s;
    __syncthreads();
    if (t == 0) {
        int tot = 0;
#pragma unroll
        for (int i = 0; i < 8; i++) tot += ws[i];
        g_bsum[b] = tot;
    }
}

// ---------------- scan pass 2 ----------------
__global__ __launch_bounds__(128) void scan2_kernel() {
    int t = threadIdx.x;
    int lane = t & 31, wid = t >> 5;
    int v = (t < N_SCAN_BLOCKS) ? g_bsum[t] : 0;
    int x = v;
#pragma unroll
    for (int o = 1; o < 32; o <<= 1) {
        int y = __shfl_up_sync(0xffffffffu, x, o);
        if (lane >= o) x += y;
    }
    __shared__ int wsum[4];
    if (lane == 31) wsum[wid] = x;
    __syncthreads();
    if (t == 0) {
        int r = 0;
#pragma unroll
        for (int i = 0; i < 4; i++) { int tmp = wsum[i]; wsum[i] = r; r += tmp; }
    }
    __syncthreads();
    int incl = x + wsum[wid];
    if (t < N_SCAN_BLOCKS) g_boff[t] = incl - v;
}

// ---------------- scan pass 3 + norm ----------------
__global__ __launch_bounds__(256) void scan3_kernel() {
    int b = blockIdx.x, t = threadIdx.x;
    int lane = t & 31, wid = t >> 5;
    int base = b * NODES_PER_SCAN_BLOCK + t * 4;
    int c[4];
    int tsum = 0;
#pragma unroll
    for (int q = 0; q < 4; q++) {
        c[q] = (base + q < N_NODES) ? g_cnt[base + q] : 0;
        tsum += c[q];
    }
    int x = tsum;
#pragma unroll
    for (int o = 1; o < 32; o <<= 1) {
        int y = __shfl_up_sync(0xffffffffu, x, o);
        if (lane >= o) x += y;
    }
    __shared__ int wsum[8], woff[8];
    if (lane == 31) wsum[wid] = x;
    __syncthreads();
    if (t == 0) {
        int r = 0;
#pragma unroll
        for (int i = 0; i < 8; i++) { woff[i] = r; r += wsum[i]; }
    }
    __syncthreads();
    int run = (x - tsum) + woff[wid] + g_boff[b];
#pragma unroll
    for (int q = 0; q < 4; q++) {
        int n = base + q;
        if (n < N_NODES) {
            g_off[n] = run;
            g_norm[n] = rsqrtf(fmaxf((float)c[q], 1.0f));
        }
        run += c[q];
    }
}

// ---------------- CSR fill ----------------
__global__ void fill_kernel(const int* __restrict__ esrc, const int* __restrict__ edst) {
    int e = blockIdx.x * blockDim.x + threadIdx.x;
    if (e < N_EDGES) {
        int d = edst[e];
        int pos = atomicAdd(&g_cur[d], 1);
        g_csr[g_off[d] + pos] = esrc[e];
    }
}

// ---------------- fused aggregate + tensor-core GEMM ----------------
// Phase 1: warps pull-aggregate 64 dst rows into smem As (no atomics).
// Phase 2: 3xTF32 mma.sync GEMM: out[64x128] = As @ W^T + b.
//   Warp layout 4(m) x 2(n); warp tile m16 x n64 (8 nfrags); K loop 16 steps of 8.
//   B frags from cp.async double-buffered smem stage of prepacked g_wpack.
#define BM 64
#define A_PAD 132

__global__ __launch_bounds__(256, 3) void fused_kernel(const float* __restrict__ h,
                                                       const float* __restrict__ bias,
                                                       float* __restrict__ out) {
    __shared__ float  As[BM][A_PAD];       // A tile, then reused to stage D
    __shared__ float4 Wbuf[2][16][32];     // per-kstep B fragments {b0h,b1h,b0l,b1l}

    int tid = threadIdx.x;
    int wid = tid >> 5;
    int lane = tid & 31;
    int block_m = blockIdx.x * BM;

    // ---- phase 1: aggregation (R2-style) ----
    for (int r = wid; r < BM; r += 8) {
        int gm = block_m + r;
        float4 acc = make_float4(0.f, 0.f, 0.f, 0.f);
        if (gm < N_NODES) {
            int beg = g_off[gm];
            int end = beg + g_cnt[gm];
            for (int j = beg; j < end; j++) {
                int src = g_csr[j];                 // warp-uniform
                float ns = g_norm[src];
                float4 v = ((const float4*)(h + (size_t)src * DIM))[lane];
                acc.x = fmaf(v.x, ns, acc.x);
                acc.y = fmaf(v.y, ns, acc.y);
                acc.z = fmaf(v.z, ns, acc.z);
                acc.w = fmaf(v.w, ns, acc.w);
            }
            float nd = g_norm[gm];
            acc.x *= nd; acc.y *= nd; acc.z *= nd; acc.w *= nd;
        }
        *(float4*)&As[r][lane * 4] = acc;
    }

    // ---- prefetch B frags for ks=0 ----
    {
        const float4* src = g_wpack;               // ks 0 -> 512 float4s
        float4* dst = &Wbuf[0][0][0];
        cpasync16(dst + tid, src + tid);
        cpasync16(dst + tid + 256, src + tid + 256);
        CP_COMMIT();
    }

    // ---- phase 2: GEMM ----
    int wm = wid >> 1;        // 0..3
    int wn = wid & 1;         // 0..1
    int g  = lane >> 2;       // 0..7
    int tg = lane & 3;        // 0..3

    float d[8][4];
#pragma unroll
    for (int f = 0; f < 8; f++)
#pragma unroll
        for (int q = 0; q < 4; q++) d[f][q] = 0.f;

#pragma unroll 1
    for (int ks = 0; ks < 16; ks++) {
        int cur = ks & 1;
        __syncthreads();      // prev compute done (and, at ks=0, As complete)
        if (ks < 15) {
            const float4* src = g_wpack + (ks + 1) * 512;
            float4* dst = &Wbuf[cur ^ 1][0][0];
            cpasync16(dst + tid, src + tid);
            cpasync16(dst + tid + 256, src + tid + 256);
        }
        CP_COMMIT();
        CP_WAIT1();           // current buffer's copies complete
        __syncthreads();      // visible to all warps

        // A fragment (fp32 -> tf32 hi/lo split)
        int row0 = wm * 16 + g;
        int k0 = ks * 8 + tg;
        float a0 = As[row0][k0];
        float a1 = As[row0 + 8][k0];
        float a2 = As[row0][k0 + 4];
        float a3 = As[row0 + 8][k0 + 4];
        uint32_t ah[4], al[4];
        ah[0] = f2tf32(a0); al[0] = f2tf32(a0 - __uint_as_float(ah[0]));
        ah[1] = f2tf32(a1); al[1] = f2tf32(a1 - __uint_as_float(ah[1]));
        ah[2] = f2tf32(a2); al[2] = f2tf32(a2 - __uint_as_float(ah[2]));
        ah[3] = f2tf32(a3); al[3] = f2tf32(a3 - __uint_as_float(ah[3]));

#pragma unroll
        for (int f = 0; f < 8; f++) {
            float4 w = Wbuf[cur][wn * 8 + f][lane];
            uint32_t bh0 = __float_as_uint(w.x);
            uint32_t bh1 = __float_as_uint(w.y);
            uint32_t bl0 = __float_as_uint(w.z);
            uint32_t bl1 = __float_as_uint(w.w);
            mma_tf32(d[f], ah, bh0, bh1);   // hi*hi
            mma_tf32(d[f], ah, bl0, bl1);   // hi*lo
            mma_tf32(d[f], al, bh0, bh1);   // lo*hi
        }
    }

    // ---- stage D back through As for coalesced output ----
    __syncthreads();
#pragma unroll
    for (int f = 0; f < 8; f++) {
        int nb = wn * 64 + f * 8 + 2 * tg;
        int r0 = wm * 16 + g;
        As[r0][nb]     = d[f][0];
        As[r0][nb + 1] = d[f][1];
        As[r0 + 8][nb]     = d[f][2];
        As[r0 + 8][nb + 1] = d[f][3];
    }
    __syncthreads();

    // ---- coalesced write-out with bias ----
    int r = tid >> 2;            // 0..63
    int cb = (tid & 3) * 32;     // 0,32,64,96
    int gm = block_m + r;
    if (gm < N_NODES) {
#pragma unroll
        for (int q = 0; q < 8; q++) {
            int c = cb + q * 4;
            float4 v = *(const float4*)&As[r][c];
            float4 bv = __ldg((const float4*)(bias + c));
            v.x += bv.x; v.y += bv.y; v.z += bv.z; v.w += bv.w;
            *(float4*)(out + (size_t)gm * DIM + c) = v;
        }
    }
}

// ---------------- launch ----------------
extern "C" void kernel_launch(void* const* d_in, const int* in_sizes, int n_in,
                              void* d_out, int out_size) {
    const float* h    = (const float*)d_in[0];
    const float* W    = (const float*)d_in[1];
    const float* bias = (const float*)d_in[2];
    const int* esrc   = (const int*)d_in[3];
    const int* edst   = (const int*)d_in[4];
    float* out = (float*)d_out;

    zero_kernel<<<256, 256>>>();
    deg_kernel<<<(N_EDGES + 255) / 256, 256>>>(edst);
    wpack_kernel<<<32, 256>>>(W);
    scan1_kernel<<<N_SCAN_BLOCKS, 256>>>();
    scan2_kernel<<<1, 128>>>();
    scan3_kernel<<<N_SCAN_BLOCKS, 256>>>();
    fill_kernel<<<(N_EDGES + 255) / 256, 256>>>(esrc, edst);
    fused_kernel<<<(N_NODES + BM - 1) / BM, 256>>>(h, bias, out);
}